// round 1
// baseline (speedup 1.0000x reference)
#include <cuda_runtime.h>
#include <math.h>

#define BB   8
#define CLEN 2048
#define QLEN 512
#define DD   1024
#define KTOT (4*DD)

// ---- scratch (static device globals; no allocation allowed) ----
__device__ float g_S[(size_t)BB*CLEN*QLEN];     // similarity / attention  [B,C,Q]
__device__ float g_M[BB*CLEN];                  // rowmax over Q
__device__ float g_Batt[BB*CLEN];               // softmax over C of rowmax
__device__ float g_C2Q[(size_t)BB*CLEN*DD];     // c2q attention output
__device__ float g_Q2Cpart[32*BB*DD];           // partial sums for q2c
__device__ float g_Q2C[BB*DD];                  // q2c attention output
__device__ float g_rowc[BB*CLEN];               // c@w_c + b_c
__device__ float g_rowq[BB*QLEN];               // q@w_q + b_q

// -------------------------------------------------------------------------
// rowc[b,c] = dot(c[b,c,:], w_c) + b_c ; rowq[b,q] = dot(q[b,q,:], w_q)+b_q
// -------------------------------------------------------------------------
__global__ void row_reduce_kernel(const float* __restrict__ c, const float* __restrict__ q,
                                  const float* __restrict__ w_c, const float* __restrict__ b_c,
                                  const float* __restrict__ w_q, const float* __restrict__ b_q) {
    int row = blockIdx.x;
    const float* src; const float* w; const float* bias; float* dst;
    if (row < BB*CLEN) { src = c + (size_t)row*DD; w = w_c; bias = b_c; dst = g_rowc + row; }
    else { int r = row - BB*CLEN; src = q + (size_t)r*DD; w = w_q; bias = b_q; dst = g_rowq + r; }
    float s = 0.f;
    for (int k = threadIdx.x; k < DD; k += 128) s += src[k]*w[k];
    __shared__ float red[128];
    red[threadIdx.x] = s; __syncthreads();
    for (int off = 64; off > 0; off >>= 1) {
        if (threadIdx.x < off) red[threadIdx.x] += red[threadIdx.x+off];
        __syncthreads();
    }
    if (threadIdx.x == 0) dst[0] = red[0] + bias[0];
}

// -------------------------------------------------------------------------
// GEMM1 (NT): S[b,m,n] = sum_k (c[b,m,k]*w_cq[k]) * q[b,n,k] + b_cq + rowc + rowq
// 128x128x8 tile, 256 threads, 8x8 per thread.
// -------------------------------------------------------------------------
__global__ __launch_bounds__(256) void gemm1_kernel(const float* __restrict__ c,
                                                    const float* __restrict__ q,
                                                    const float* __restrict__ w_cq,
                                                    const float* __restrict__ b_cq) {
    int b  = blockIdx.z;
    int m0 = blockIdx.y * 128;
    int n0 = blockIdx.x * 128;
    const float* A  = c + (size_t)b*CLEN*DD;
    const float* Bq = q + (size_t)b*QLEN*DD;
    __shared__ float As[8][128];
    __shared__ float Bs[8][128];
    int tid = threadIdx.x;
    int tx = tid & 15, ty = tid >> 4;
    int lrow = tid >> 1;
    int lcol = (tid & 1) * 4;
    float acc[8][8];
    #pragma unroll
    for (int i=0;i<8;i++)
        #pragma unroll
        for (int j=0;j<8;j++) acc[i][j]=0.f;

    for (int k0 = 0; k0 < DD; k0 += 8) {
        float4 av = *(const float4*)(A  + (size_t)(m0+lrow)*DD + k0 + lcol);
        float4 wv = *(const float4*)(w_cq + k0 + lcol);
        As[lcol+0][lrow] = av.x*wv.x;
        As[lcol+1][lrow] = av.y*wv.y;
        As[lcol+2][lrow] = av.z*wv.z;
        As[lcol+3][lrow] = av.w*wv.w;
        float4 bv = *(const float4*)(Bq + (size_t)(n0+lrow)*DD + k0 + lcol);
        Bs[lcol+0][lrow] = bv.x;
        Bs[lcol+1][lrow] = bv.y;
        Bs[lcol+2][lrow] = bv.z;
        Bs[lcol+3][lrow] = bv.w;
        __syncthreads();
        #pragma unroll
        for (int k=0;k<8;k++){
            float a[8], bb[8];
            *(float4*)&a[0]  = *(const float4*)&As[k][ty*8];
            *(float4*)&a[4]  = *(const float4*)&As[k][ty*8+4];
            *(float4*)&bb[0] = *(const float4*)&Bs[k][tx*8];
            *(float4*)&bb[4] = *(const float4*)&Bs[k][tx*8+4];
            #pragma unroll
            for (int i=0;i<8;i++)
                #pragma unroll
                for (int j=0;j<8;j++) acc[i][j] += a[i]*bb[j];
        }
        __syncthreads();
    }
    float bias = b_cq[0];
    #pragma unroll
    for (int i=0;i<8;i++){
        int m = m0 + ty*8 + i;
        float rc = g_rowc[b*CLEN + m] + bias;
        float* outp = g_S + ((size_t)b*CLEN + m)*QLEN + n0;
        #pragma unroll
        for (int j=0;j<8;j++){
            int n = n0 + tx*8 + j;
            outp[tx*8+j] = acc[i][j] + rc + g_rowq[b*QLEN + n];
        }
    }
}

// -------------------------------------------------------------------------
// softmax over Q (512) per (b,c) row; record rowmax
// -------------------------------------------------------------------------
__global__ void softmax_q_kernel() {
    int row = blockIdx.x;
    float* s = g_S + (size_t)row*QLEN;
    int t = threadIdx.x;            // 128 threads, 4 elems each
    float v[4];
    float m = -1e30f;
    #pragma unroll
    for (int i=0;i<4;i++){ v[i] = s[t + i*128]; m = fmaxf(m, v[i]); }
    __shared__ float red[128];
    red[t] = m; __syncthreads();
    for (int off=64; off>0; off>>=1){ if (t<off) red[t]=fmaxf(red[t],red[t+off]); __syncthreads(); }
    float rowmax = red[0];
    __syncthreads();
    float sum = 0.f;
    #pragma unroll
    for (int i=0;i<4;i++){ v[i] = __expf(v[i]-rowmax); sum += v[i]; }
    red[t]=sum; __syncthreads();
    for (int off=64; off>0; off>>=1){ if (t<off) red[t]+=red[t+off]; __syncthreads(); }
    float inv = 1.f/red[0];
    #pragma unroll
    for (int i=0;i<4;i++) s[t+i*128] = v[i]*inv;
    if (t==0) g_M[row]=rowmax;
}

// -------------------------------------------------------------------------
// b_att[b,:] = softmax over C of g_M[b,:]
// -------------------------------------------------------------------------
__global__ void batt_kernel() {
    int b = blockIdx.x;
    int t = threadIdx.x;            // 256 threads, 8 elems each
    float v[8]; float m = -1e30f;
    #pragma unroll
    for (int i=0;i<8;i++){ v[i]=g_M[b*CLEN + t + i*256]; m=fmaxf(m,v[i]); }
    __shared__ float red[256];
    red[t]=m; __syncthreads();
    for (int off=128; off>0; off>>=1){ if (t<off) red[t]=fmaxf(red[t],red[t+off]); __syncthreads(); }
    float mx = red[0];
    __syncthreads();
    float sum = 0.f;
    #pragma unroll
    for (int i=0;i<8;i++){ v[i]=__expf(v[i]-mx); sum+=v[i]; }
    red[t]=sum; __syncthreads();
    for (int off=128; off>0; off>>=1){ if (t<off) red[t]+=red[t+off]; __syncthreads(); }
    float inv = 1.f/red[0];
    #pragma unroll
    for (int i=0;i<8;i++) g_Batt[b*CLEN + t + i*256] = v[i]*inv;
}

// -------------------------------------------------------------------------
// q2c partial: each block (j,b) handles 64 context rows, accumulates over d
// -------------------------------------------------------------------------
__global__ void q2c_part_kernel(const float* __restrict__ c) {
    int j = blockIdx.x;     // 0..31
    int b = blockIdx.y;
    int t = threadIdx.x;    // 256
    float acc[4] = {0.f,0.f,0.f,0.f};
    int cbase = j*64;
    const float* cb = c + ((size_t)b*CLEN + cbase)*DD;
    for (int cc=0; cc<64; cc++){
        float w = g_Batt[b*CLEN + cbase + cc];
        const float* row = cb + (size_t)cc*DD;
        #pragma unroll
        for (int i=0;i<4;i++) acc[i] += w * row[t + i*256];
    }
    #pragma unroll
    for (int i=0;i<4;i++) g_Q2Cpart[((size_t)j*BB + b)*DD + t + i*256] = acc[i];
}

__global__ void q2c_reduce_kernel() {
    int idx = blockIdx.x*256 + threadIdx.x;   // < BB*DD
    int b = idx / DD, d = idx % DD;
    float s = 0.f;
    for (int j=0;j<32;j++) s += g_Q2Cpart[((size_t)j*BB + b)*DD + d];
    g_Q2C[idx] = s;
}

// -------------------------------------------------------------------------
// GEMM2 (NN): C2Q[b,m,n] = sum_q a[b,m,q] * q[b,q,n]
// -------------------------------------------------------------------------
__global__ __launch_bounds__(256) void gemm2_kernel(const float* __restrict__ q) {
    int b  = blockIdx.z;
    int m0 = blockIdx.y * 128;
    int n0 = blockIdx.x * 128;
    const float* A  = g_S + (size_t)b*CLEN*QLEN;
    const float* Bq = q   + (size_t)b*QLEN*DD;
    __shared__ float As[8][128];
    __shared__ float Bs[8][128];
    int tid = threadIdx.x;
    int tx = tid & 15, ty = tid >> 4;
    int lrow = tid >> 1;
    int lcol = (tid & 1) * 4;
    int krow = tid >> 5;          // 0..7
    int ncol = (tid & 31) * 4;    // 0..124
    float acc[8][8];
    #pragma unroll
    for (int i=0;i<8;i++)
        #pragma unroll
        for (int j=0;j<8;j++) acc[i][j]=0.f;

    for (int k0 = 0; k0 < QLEN; k0 += 8) {
        float4 av = *(const float4*)(A + (size_t)(m0+lrow)*QLEN + k0 + lcol);
        As[lcol+0][lrow] = av.x;
        As[lcol+1][lrow] = av.y;
        As[lcol+2][lrow] = av.z;
        As[lcol+3][lrow] = av.w;
        float4 bv = *(const float4*)(Bq + (size_t)(k0+krow)*DD + n0 + ncol);
        *(float4*)&Bs[krow][ncol] = bv;
        __syncthreads();
        #pragma unroll
        for (int k=0;k<8;k++){
            float a[8], bb[8];
            *(float4*)&a[0]  = *(const float4*)&As[k][ty*8];
            *(float4*)&a[4]  = *(const float4*)&As[k][ty*8+4];
            *(float4*)&bb[0] = *(const float4*)&Bs[k][tx*8];
            *(float4*)&bb[4] = *(const float4*)&Bs[k][tx*8+4];
            #pragma unroll
            for (int i=0;i<8;i++)
                #pragma unroll
                for (int j=0;j<8;j++) acc[i][j] += a[i]*bb[j];
        }
        __syncthreads();
    }
    #pragma unroll
    for (int i=0;i<8;i++){
        int m = m0 + ty*8 + i;
        float* outp = g_C2Q + ((size_t)b*CLEN + m)*DD + n0;
        #pragma unroll
        for (int j=0;j<8;j++) outp[tx*8+j] = acc[i][j];
    }
}

// -------------------------------------------------------------------------
// GEMM3 (NT, on-the-fly A): z[m,n] = sum_k x[m,k] * W_l[n,k] + b_l[n]
// x[m, 0:D]=c ; [D:2D]=c2q ; [2D:3D]=c*c2q ; [3D:4D]=c*q2c[b]
// -------------------------------------------------------------------------
__global__ __launch_bounds__(256) void gemm3_kernel(const float* __restrict__ c,
                                                    const float* __restrict__ W_l,
                                                    const float* __restrict__ b_l,
                                                    float* __restrict__ out) {
    int m0 = blockIdx.y * 128;     // over B*CLEN
    int n0 = blockIdx.x * 128;     // over DD
    int bq = m0 / CLEN;            // tile fully inside one batch (2048 % 128 == 0)
    __shared__ float As[8][128];
    __shared__ float Bs[8][128];
    int tid = threadIdx.x;
    int tx = tid & 15, ty = tid >> 4;
    int lrow = tid >> 1;
    int lcol = (tid & 1) * 4;
    float acc[8][8];
    #pragma unroll
    for (int i=0;i<8;i++)
        #pragma unroll
        for (int j=0;j<8;j++) acc[i][j]=0.f;

    int grow = m0 + lrow;
    const float* crow   = c      + (size_t)grow*DD;
    const float* c2qrow = g_C2Q  + (size_t)grow*DD;
    const float* q2c    = g_Q2C  + bq*DD;

    for (int k0 = 0; k0 < KTOT; k0 += 8) {
        int seg = k0 >> 10;
        int kk  = (k0 & 1023) + lcol;
        float4 xv;
        if (seg == 0) {
            xv = *(const float4*)(crow + kk);
        } else if (seg == 1) {
            xv = *(const float4*)(c2qrow + kk);
        } else if (seg == 2) {
            float4 cv = *(const float4*)(crow + kk);
            float4 av = *(const float4*)(c2qrow + kk);
            xv = make_float4(cv.x*av.x, cv.y*av.y, cv.z*av.z, cv.w*av.w);
        } else {
            float4 cv = *(const float4*)(crow + kk);
            float4 qv = *(const float4*)(q2c + kk);
            xv = make_float4(cv.x*qv.x, cv.y*qv.y, cv.z*qv.z, cv.w*qv.w);
        }
        As[lcol+0][lrow] = xv.x;
        As[lcol+1][lrow] = xv.y;
        As[lcol+2][lrow] = xv.z;
        As[lcol+3][lrow] = xv.w;
        float4 wv = *(const float4*)(W_l + (size_t)(n0+lrow)*KTOT + k0 + lcol);
        Bs[lcol+0][lrow] = wv.x;
        Bs[lcol+1][lrow] = wv.y;
        Bs[lcol+2][lrow] = wv.z;
        Bs[lcol+3][lrow] = wv.w;
        __syncthreads();
        #pragma unroll
        for (int k=0;k<8;k++){
            float a[8], bb[8];
            *(float4*)&a[0]  = *(const float4*)&As[k][ty*8];
            *(float4*)&a[4]  = *(const float4*)&As[k][ty*8+4];
            *(float4*)&bb[0] = *(const float4*)&Bs[k][tx*8];
            *(float4*)&bb[4] = *(const float4*)&Bs[k][tx*8+4];
            #pragma unroll
            for (int i=0;i<8;i++)
                #pragma unroll
                for (int j=0;j<8;j++) acc[i][j] += a[i]*bb[j];
        }
        __syncthreads();
    }
    #pragma unroll
    for (int i=0;i<8;i++){
        int m = m0 + ty*8 + i;
        float* orow = out + (size_t)m*DD + n0;
        #pragma unroll
        for (int j=0;j<8;j++){
            int n = n0 + tx*8 + j;
            orow[tx*8+j] = acc[i][j] + b_l[n];
        }
    }
}

// -------------------------------------------------------------------------
extern "C" void kernel_launch(void* const* d_in, const int* in_sizes, int n_in,
                              void* d_out, int out_size) {
    const float* c    = (const float*)d_in[0];
    const float* q    = (const float*)d_in[1];
    const float* w_cq = (const float*)d_in[2];
    const float* b_cq = (const float*)d_in[3];
    const float* w_c  = (const float*)d_in[4];
    const float* b_c  = (const float*)d_in[5];
    const float* w_q  = (const float*)d_in[6];
    const float* b_q  = (const float*)d_in[7];
    const float* W_l  = (const float*)d_in[8];
    const float* b_l  = (const float*)d_in[9];
    float* out = (float*)d_out;

    row_reduce_kernel<<<BB*CLEN + BB*QLEN, 128>>>(c, q, w_c, b_c, w_q, b_q);
    gemm1_kernel<<<dim3(QLEN/128, CLEN/128, BB), 256>>>(c, q, w_cq, b_cq);
    softmax_q_kernel<<<BB*CLEN, 128>>>();
    batt_kernel<<<BB, 256>>>();
    q2c_part_kernel<<<dim3(32, BB), 256>>>(c);
    q2c_reduce_kernel<<<(BB*DD)/256, 256>>>();
    gemm2_kernel<<<dim3(DD/128, CLEN/128, BB), 256>>>(q);
    gemm3_kernel<<<dim3(DD/128, (BB*CLEN)/128), 256>>>(c, W_l, b_l, out);
}

// round 5
// speedup vs baseline: 2.5433x; 2.5433x over previous
#include <cuda_runtime.h>
#include <cstdint>
#include <math.h>

#define BB   8
#define CLEN 2048
#define QLEN 512
#define DD   1024
#define KTOT (4*DD)

// ---- scratch (static device globals; no allocation allowed) ----
__device__ float g_S[(size_t)BB*CLEN*QLEN];     // similarity / attention  [B,C,Q]
__device__ float g_M[BB*CLEN];                  // rowmax over Q
__device__ float g_Batt[BB*CLEN];               // softmax over C of rowmax
__device__ float g_C2Q[(size_t)BB*CLEN*DD];     // c2q attention output
__device__ float g_Q2Cpart[32*BB*DD];           // partial sums for q2c
__device__ float g_Q2C[BB*DD];                  // q2c attention output
__device__ float g_rowc[BB*CLEN];               // c@w_c + b_c
__device__ float g_rowq[BB*QLEN];               // q@w_q + b_q
__device__ float g_qT[(size_t)BB*DD*QLEN];      // q transposed [B, D, Q]

// ============================ helpers ============================
__device__ __forceinline__ float f2tf32(float x) {
    uint32_t t;
    asm("cvt.rna.tf32.f32 %0, %1;" : "=r"(t) : "f"(x));
    return __uint_as_float(t);
}

__device__ __forceinline__ void mma_tf32(float* d, const uint32_t* a, const uint32_t* b) {
    asm volatile(
        "mma.sync.aligned.m16n8k8.row.col.f32.tf32.tf32.f32 "
        "{%0,%1,%2,%3}, {%4,%5,%6,%7}, {%8,%9}, {%0,%1,%2,%3};"
        : "+f"(d[0]), "+f"(d[1]), "+f"(d[2]), "+f"(d[3])
        : "r"(a[0]), "r"(a[1]), "r"(a[2]), "r"(a[3]), "r"(b[0]), "r"(b[1]));
}

// ============================ global loaders ============================
// A tile: 128 rows (M) x 16 floats (K); each thread loads rows ar, ar+64 at k offset ak (4 floats)
template<int MODE>
__device__ __forceinline__ void loadA_g(float4* v, const float* __restrict__ c,
                                        const float* __restrict__ w_cq,
                                        int b, int m0, int ar, int ak, int kt) {
    #pragma unroll
    for (int h = 0; h < 2; h++) {
        int r = ar + h * 64;
        int k = kt * 16 + ak;
        if (MODE == 1) {
            float4 t = *(const float4*)(c + ((size_t)(b * CLEN + m0 + r)) * DD + k);
            float4 w = *(const float4*)(w_cq + k);
            v[h] = make_float4(t.x * w.x, t.y * w.y, t.z * w.z, t.w * w.w);
        } else if (MODE == 2) {
            v[h] = *(const float4*)(g_S + ((size_t)(b * CLEN + m0 + r)) * QLEN + k);
        } else {
            int row = m0 + r;
            int seg = k >> 10;
            int kk  = k & 1023;
            if (seg == 0) {
                v[h] = *(const float4*)(c + (size_t)row * DD + kk);
            } else if (seg == 1) {
                v[h] = *(const float4*)(g_C2Q + (size_t)row * DD + kk);
            } else if (seg == 2) {
                float4 cv = *(const float4*)(c + (size_t)row * DD + kk);
                float4 av = *(const float4*)(g_C2Q + (size_t)row * DD + kk);
                v[h] = make_float4(cv.x * av.x, cv.y * av.y, cv.z * av.z, cv.w * av.w);
            } else {
                float4 cv = *(const float4*)(c + (size_t)row * DD + kk);
                float4 qv = *(const float4*)(g_Q2C + (size_t)b * DD + kk);
                v[h] = make_float4(cv.x * qv.x, cv.y * qv.y, cv.z * qv.z, cv.w * qv.w);
            }
        }
    }
}

// B tile: 128 rows (N) x 16 floats (K), row n holds B[n][k] (k-major)
template<int MODE>
__device__ __forceinline__ void loadB_g(float4* v, const float* __restrict__ q,
                                        const float* __restrict__ Wl,
                                        int b, int n0, int ar, int ak, int kt) {
    #pragma unroll
    for (int h = 0; h < 2; h++) {
        int r = ar + h * 64;
        int k = kt * 16 + ak;
        if (MODE == 1) {
            v[h] = *(const float4*)(q + ((size_t)(b * QLEN + n0 + r)) * DD + k);
        } else if (MODE == 2) {
            v[h] = *(const float4*)(g_qT + ((size_t)b * DD + n0 + r) * QLEN + k);
        } else {
            v[h] = *(const float4*)(Wl + (size_t)(n0 + r) * KTOT + k);
        }
    }
}

// ============================ tensor-core GEMM (tf32 mma.sync) ============================
// MODE 1: S = (c .* w_cq) @ q^T    (+ b_cq + rowc + rowq epilogue)   K=DD
// MODE 2: C2Q = A(softmax S) @ qT^T                                  K=QLEN
// MODE 3: out = x @ W_l^T + b_l   (x built on the fly)               K=4*DD
// CTA: 128x128 tile, BK=16, 256 threads, 8 warps (2x4), warp tile 64x32.
template<int MODE, int KTOTAL>
__global__ __launch_bounds__(256, 2)
void mma_gemm(const float* __restrict__ c, const float* __restrict__ q,
              const float* __restrict__ Wl, const float* __restrict__ w_cq,
              const float* __restrict__ b_cq, const float* __restrict__ b_l,
              float* __restrict__ outp) {
    __shared__ float As[2][128][17];
    __shared__ float Bs[2][128][17];

    const int tid  = threadIdx.x;
    const int lane = tid & 31;
    const int wid  = tid >> 5;
    const int wm   = wid >> 2;        // 0..1  (64 M-rows each)
    const int wn   = wid & 3;         // 0..3  (32 N-cols each)

    int n0 = blockIdx.x * 128, m0, b;
    if (MODE == 3) { m0 = blockIdx.y * 128; b = m0 / CLEN; }
    else           { b = blockIdx.z; m0 = blockIdx.y * 128; }

    const int ar = tid >> 2;          // 0..63
    const int ak = (tid & 3) * 4;     // 0,4,8,12

    float acc[4][4][4];
    #pragma unroll
    for (int i = 0; i < 4; i++)
        #pragma unroll
        for (int j = 0; j < 4; j++)
            #pragma unroll
            for (int l = 0; l < 4; l++) acc[i][j][l] = 0.f;

    const int NT = KTOTAL / 16;
    float4 pa[2], pb[2];
    loadA_g<MODE>(pa, c, w_cq, b, m0, ar, ak, 0);
    loadB_g<MODE>(pb, q, Wl, b, n0, ar, ak, 0);

    int p = 0;
    for (int kt = 0; kt < NT; kt++) {
        // commit prefetched tile to smem (tf32-rounded)
        #pragma unroll
        for (int h = 0; h < 2; h++) {
            int r = ar + h * 64;
            As[p][r][ak + 0] = f2tf32(pa[h].x);
            As[p][r][ak + 1] = f2tf32(pa[h].y);
            As[p][r][ak + 2] = f2tf32(pa[h].z);
            As[p][r][ak + 3] = f2tf32(pa[h].w);
            Bs[p][r][ak + 0] = f2tf32(pb[h].x);
            Bs[p][r][ak + 1] = f2tf32(pb[h].y);
            Bs[p][r][ak + 2] = f2tf32(pb[h].z);
            Bs[p][r][ak + 3] = f2tf32(pb[h].w);
        }
        __syncthreads();

        if (kt + 1 < NT) {
            loadA_g<MODE>(pa, c, w_cq, b, m0, ar, ak, kt + 1);
            loadB_g<MODE>(pb, q, Wl, b, n0, ar, ak, kt + 1);
        }

        // compute on buffer p
        #pragma unroll
        for (int k8 = 0; k8 < 16; k8 += 8) {
            uint32_t af[4][4], bf[4][2];
            #pragma unroll
            for (int mt = 0; mt < 4; mt++) {
                int row = wm * 64 + mt * 16 + (lane >> 2);
                int col = k8 + (lane & 3);
                af[mt][0] = __float_as_uint(As[p][row][col]);
                af[mt][1] = __float_as_uint(As[p][row + 8][col]);
                af[mt][2] = __float_as_uint(As[p][row][col + 4]);
                af[mt][3] = __float_as_uint(As[p][row + 8][col + 4]);
            }
            #pragma unroll
            for (int nt = 0; nt < 4; nt++) {
                int n = wn * 32 + nt * 8 + (lane >> 2);
                int col = k8 + (lane & 3);
                bf[nt][0] = __float_as_uint(Bs[p][n][col]);
                bf[nt][1] = __float_as_uint(Bs[p][n][col + 4]);
            }
            #pragma unroll
            for (int mt = 0; mt < 4; mt++)
                #pragma unroll
                for (int nt = 0; nt < 4; nt++)
                    mma_tf32(acc[mt][nt], af[mt], bf[nt]);
        }
        p ^= 1;
    }

    // ---- epilogue ----
    #pragma unroll
    for (int mt = 0; mt < 4; mt++) {
        int mloc0 = wm * 64 + mt * 16 + (lane >> 2);
        #pragma unroll
        for (int half = 0; half < 2; half++) {
            int mloc = mloc0 + half * 8;
            float v0, v1;
            #pragma unroll
            for (int nt = 0; nt < 4; nt++) {
                v0 = acc[mt][nt][half * 2 + 0];
                v1 = acc[mt][nt][half * 2 + 1];
                int col = n0 + wn * 32 + nt * 8 + (lane & 3) * 2;
                if (MODE == 1) {
                    float rb = b_cq[0] + g_rowc[b * CLEN + m0 + mloc];
                    float2 o = make_float2(v0 + rb + g_rowq[b * QLEN + col],
                                           v1 + rb + g_rowq[b * QLEN + col + 1]);
                    *(float2*)(g_S + ((size_t)(b * CLEN + m0 + mloc)) * QLEN + col) = o;
                } else if (MODE == 2) {
                    *(float2*)(g_C2Q + ((size_t)(b * CLEN + m0 + mloc)) * DD + col) =
                        make_float2(v0, v1);
                } else {
                    float2 o = make_float2(v0 + b_l[col], v1 + b_l[col + 1]);
                    *(float2*)(outp + ((size_t)(m0 + mloc)) * DD + col) = o;
                }
            }
        }
    }
}

// ============================ small kernels ============================
__global__ void row_reduce_kernel(const float* __restrict__ c, const float* __restrict__ q,
                                  const float* __restrict__ w_c, const float* __restrict__ b_c,
                                  const float* __restrict__ w_q, const float* __restrict__ b_q) {
    int row = blockIdx.x;
    const float* src; const float* w; const float* bias; float* dst;
    if (row < BB*CLEN) { src = c + (size_t)row*DD; w = w_c; bias = b_c; dst = g_rowc + row; }
    else { int r = row - BB*CLEN; src = q + (size_t)r*DD; w = w_q; bias = b_q; dst = g_rowq + r; }
    float s = 0.f;
    for (int k = threadIdx.x; k < DD; k += 128) s += src[k]*w[k];
    __shared__ float red[128];
    red[threadIdx.x] = s; __syncthreads();
    for (int off = 64; off > 0; off >>= 1) {
        if (threadIdx.x < off) red[threadIdx.x] += red[threadIdx.x+off];
        __syncthreads();
    }
    if (threadIdx.x == 0) dst[0] = red[0] + bias[0];
}

__global__ void transpose_q_kernel(const float* __restrict__ q) {
    __shared__ float t[32][33];
    int b = blockIdx.z;
    int q0 = blockIdx.x * 32, d0 = blockIdx.y * 32;
    for (int i = threadIdx.y; i < 32; i += 8)
        t[i][threadIdx.x] = q[((size_t)b*QLEN + q0 + i)*DD + d0 + threadIdx.x];
    __syncthreads();
    for (int i = threadIdx.y; i < 32; i += 8)
        g_qT[((size_t)b*DD + d0 + i)*QLEN + q0 + threadIdx.x] = t[threadIdx.x][i];
}

__global__ void softmax_q_kernel() {
    int row = blockIdx.x;
    float* s = g_S + (size_t)row*QLEN;
    int t = threadIdx.x;
    float v[4];
    float m = -1e30f;
    #pragma unroll
    for (int i=0;i<4;i++){ v[i] = s[t + i*128]; m = fmaxf(m, v[i]); }
    __shared__ float red[128];
    red[t] = m; __syncthreads();
    for (int off=64; off>0; off>>=1){ if (t<off) red[t]=fmaxf(red[t],red[t+off]); __syncthreads(); }
    float rowmax = red[0];
    __syncthreads();
    float sum = 0.f;
    #pragma unroll
    for (int i=0;i<4;i++){ v[i] = __expf(v[i]-rowmax); sum += v[i]; }
    red[t]=sum; __syncthreads();
    for (int off=64; off>0; off>>=1){ if (t<off) red[t]+=red[t+off]; __syncthreads(); }
    float inv = 1.f/red[0];
    #pragma unroll
    for (int i=0;i<4;i++) s[t+i*128] = v[i]*inv;
    if (t==0) g_M[row]=rowmax;
}

__global__ void batt_kernel() {
    int b = blockIdx.x;
    int t = threadIdx.x;
    float v[8]; float m = -1e30f;
    #pragma unroll
    for (int i=0;i<8;i++){ v[i]=g_M[b*CLEN + t + i*256]; m=fmaxf(m,v[i]); }
    __shared__ float red[256];
    red[t]=m; __syncthreads();
    for (int off=128; off>0; off>>=1){ if (t<off) red[t]=fmaxf(red[t],red[t+off]); __syncthreads(); }
    float mx = red[0];
    __syncthreads();
    float sum = 0.f;
    #pragma unroll
    for (int i=0;i<8;i++){ v[i]=__expf(v[i]-mx); sum+=v[i]; }
    red[t]=sum; __syncthreads();
    for (int off=128; off>0; off>>=1){ if (t<off) red[t]+=red[t+off]; __syncthreads(); }
    float inv = 1.f/red[0];
    #pragma unroll
    for (int i=0;i<8;i++) g_Batt[b*CLEN + t + i*256] = v[i]*inv;
}

__global__ void q2c_part_kernel(const float* __restrict__ c) {
    int j = blockIdx.x;
    int b = blockIdx.y;
    int t = threadIdx.x;
    float acc[4] = {0.f,0.f,0.f,0.f};
    int cbase = j*64;
    const float* cb = c + ((size_t)b*CLEN + cbase)*DD;
    for (int cc=0; cc<64; cc++){
        float w = g_Batt[b*CLEN + cbase + cc];
        const float* row = cb + (size_t)cc*DD;
        #pragma unroll
        for (int i=0;i<4;i++) acc[i] += w * row[t + i*256];
    }
    #pragma unroll
    for (int i=0;i<4;i++) g_Q2Cpart[((size_t)j*BB + b)*DD + t + i*256] = acc[i];
}

__global__ void q2c_reduce_kernel() {
    int idx = blockIdx.x*256 + threadIdx.x;
    int b = idx / DD, d = idx % DD;
    float s = 0.f;
    for (int j=0;j<32;j++) s += g_Q2Cpart[((size_t)j*BB + b)*DD + d];
    g_Q2C[idx] = s;
}

// ============================ launch ============================
extern "C" void kernel_launch(void* const* d_in, const int* in_sizes, int n_in,
                              void* d_out, int out_size) {
    const float* c    = (const float*)d_in[0];
    const float* q    = (const float*)d_in[1];
    const float* w_cq = (const float*)d_in[2];
    const float* b_cq = (const float*)d_in[3];
    const float* w_c  = (const float*)d_in[4];
    const float* b_c  = (const float*)d_in[5];
    const float* w_q  = (const float*)d_in[6];
    const float* b_q  = (const float*)d_in[7];
    const float* W_l  = (const float*)d_in[8];
    const float* b_l  = (const float*)d_in[9];
    float* out = (float*)d_out;

    row_reduce_kernel<<<BB*CLEN + BB*QLEN, 128>>>(c, q, w_c, b_c, w_q, b_q);
    transpose_q_kernel<<<dim3(QLEN/32, DD/32, BB), dim3(32, 8)>>>(q);

    mma_gemm<1, DD><<<dim3(QLEN/128, CLEN/128, BB), 256>>>(
        c, q, W_l, w_cq, b_cq, b_l, out);

    softmax_q_kernel<<<BB*CLEN, 128>>>();
    batt_kernel<<<BB, 256>>>();
    q2c_part_kernel<<<dim3(32, BB), 256>>>(c);
    q2c_reduce_kernel<<<(BB*DD)/256, 256>>>();

    mma_gemm<2, QLEN><<<dim3(DD/128, CLEN/128, BB), 256>>>(
        c, q, W_l, w_cq, b_cq, b_l, out);

    mma_gemm<3, KTOT><<<dim3(DD/128, (BB*CLEN)/128, 1), 256>>>(
        c, q, W_l, w_cq, b_cq, b_l, out);
}

// round 7
// speedup vs baseline: 2.6442x; 1.0397x over previous
#include <cuda_runtime.h>
#include <cstdint>
#include <math.h>

#define BB   8
#define CLEN 2048
#define QLEN 512
#define DD   1024
#define KTOT (4*DD)

// ---- scratch (static device globals; no allocation allowed) ----
__device__ float g_S[(size_t)BB*CLEN*QLEN];     // similarity / attention  [B,C,Q]
__device__ float g_M[BB*CLEN];                  // rowmax over Q
__device__ float g_Batt[BB*CLEN];               // softmax over C of rowmax
__device__ float g_C2Q[(size_t)BB*CLEN*DD];     // c2q attention output
__device__ float g_Q2Cpart[32*BB*DD];           // partial sums for q2c
__device__ float g_Q2C[BB*DD];                  // q2c attention output
__device__ float g_rowc[BB*CLEN];               // c@w_c + b_c
__device__ float g_rowq[BB*QLEN];               // q@w_q + b_q
__device__ float g_qT[(size_t)BB*DD*QLEN];      // q transposed [B, D, Q]

// ============================ helpers ============================
__device__ __forceinline__ float f2tf32(float x) {
    uint32_t t;
    asm("cvt.rna.tf32.f32 %0, %1;" : "=r"(t) : "f"(x));
    return __uint_as_float(t);
}

__device__ __forceinline__ void mma_tf32(float* d, const uint32_t* a, const uint32_t* b) {
    asm volatile(
        "mma.sync.aligned.m16n8k8.row.col.f32.tf32.tf32.f32 "
        "{%0,%1,%2,%3}, {%4,%5,%6,%7}, {%8,%9}, {%0,%1,%2,%3};"
        : "+f"(d[0]), "+f"(d[1]), "+f"(d[2]), "+f"(d[3])
        : "r"(a[0]), "r"(a[1]), "r"(a[2]), "r"(a[3]), "r"(b[0]), "r"(b[1]));
}

// ============================ global loaders ============================
// A tile: 128 rows (M) x 16 floats (K); thread loads rows ar, ar+64 at k offset ak (4 floats)
template<int MODE>
__device__ __forceinline__ void loadA_g(float4* v, const float* __restrict__ c,
                                        const float* __restrict__ w_cq,
                                        int b, int m0, int ar, int ak, int kt) {
    #pragma unroll
    for (int h = 0; h < 2; h++) {
        int r = ar + h * 64;
        int k = kt * 16 + ak;
        if (MODE == 1) {
            float4 t = *(const float4*)(c + ((size_t)(b * CLEN + m0 + r)) * DD + k);
            float4 w = *(const float4*)(w_cq + k);
            v[h] = make_float4(t.x * w.x, t.y * w.y, t.z * w.z, t.w * w.w);
        } else if (MODE == 2) {
            v[h] = *(const float4*)(g_S + ((size_t)(b * CLEN + m0 + r)) * QLEN + k);
        } else {
            int row = m0 + r;
            int seg = k >> 10;
            int kk  = k & 1023;
            if (seg == 0) {
                v[h] = *(const float4*)(c + (size_t)row * DD + kk);
            } else if (seg == 1) {
                v[h] = *(const float4*)(g_C2Q + (size_t)row * DD + kk);
            } else if (seg == 2) {
                float4 cv = *(const float4*)(c + (size_t)row * DD + kk);
                float4 av = *(const float4*)(g_C2Q + (size_t)row * DD + kk);
                v[h] = make_float4(cv.x * av.x, cv.y * av.y, cv.z * av.z, cv.w * av.w);
            } else {
                float4 cv = *(const float4*)(c + (size_t)row * DD + kk);
                float4 qv = *(const float4*)(g_Q2C + (size_t)b * DD + kk);
                v[h] = make_float4(cv.x * qv.x, cv.y * qv.y, cv.z * qv.z, cv.w * qv.w);
            }
        }
    }
}

// B tile: 128 rows (N) x 16 floats (K), row n holds B[n][k] (k-major)
template<int MODE>
__device__ __forceinline__ void loadB_g(float4* v, const float* __restrict__ q,
                                        const float* __restrict__ Wl,
                                        int b, int n0, int ar, int ak, int kt) {
    #pragma unroll
    for (int h = 0; h < 2; h++) {
        int r = ar + h * 64;
        int k = kt * 16 + ak;
        if (MODE == 1) {
            v[h] = *(const float4*)(q + ((size_t)(b * QLEN + n0 + r)) * DD + k);
        } else if (MODE == 2) {
            v[h] = *(const float4*)(g_qT + ((size_t)b * DD + n0 + r) * QLEN + k);
        } else {
            v[h] = *(const float4*)(Wl + (size_t)(n0 + r) * KTOT + k);
        }
    }
}

// ============================ tensor-core GEMM (tf32 mma.sync) ============================
// Fragment-major smem layout:
//  A elem (r,k): chunk=( (r>>4)*2 + (k>>3) ), qi=(r&7)*4 + ((k&3)^(r&3)), sub=((k>>2)&1)*2 + ((r>>3)&1)
//    float idx = (chunk*32 + qi)*4 + sub                       [2048 floats/stage]
//  B elem (n,k): chunk=( (n>>3)*2 + (k>>3) ), pi=(n&7)*4 + ((k&3)^(n&3)), sub=(k>>2)&1
//    float idx = (chunk*32 + pi)*2 + sub                       [2048 floats/stage]
// Consumer: A fragment = one LDS.128, B fragment = one LDS.64, both conflict-free.
template<int MODE, int KTOTAL>
__global__ __launch_bounds__(256, 2)
void mma_gemm(const float* __restrict__ c, const float* __restrict__ q,
              const float* __restrict__ Wl, const float* __restrict__ w_cq,
              const float* __restrict__ b_cq, const float* __restrict__ b_l,
              float* __restrict__ outp) {
    __shared__ __align__(16) float As[2][2048];
    __shared__ __align__(16) float Bs[2][2048];

    const int tid  = threadIdx.x;
    const int lane = tid & 31;
    const int wid  = tid >> 5;
    const int wm   = wid >> 2;        // 0..1  (64 M-rows each)
    const int wn   = wid & 3;         // 0..3  (32 N-cols each)

    int n0 = blockIdx.x * 128, m0, b;
    if (MODE == 3) { m0 = blockIdx.y * 128; b = m0 / CLEN; }
    else           { b = blockIdx.z; m0 = blockIdx.y * 128; }

    const int ar = tid >> 2;          // 0..63
    const int ak = (tid & 3) * 4;     // 0,4,8,12
    const int ck_p    = ak >> 3;          // k-block of this thread's 4 floats
    const int chalf_p = (ak >> 2) & 1;

    // producer bases for the two row-halves (r = ar, ar+64)
    int aBase[2], bBase[2], xsel[2];
    #pragma unroll
    for (int h = 0; h < 2; h++) {
        int r = ar + h * 64;
        int cr = r >> 4, l7 = r & 7, rhalf = (r >> 3) & 1;
        int cn = r >> 3;
        aBase[h] = ((cr * 2 + ck_p) * 32 + l7 * 4) * 4 + chalf_p * 2 + rhalf;
        bBase[h] = ((cn * 2 + ck_p) * 32 + l7 * 4) * 2 + chalf_p;
        xsel[h]  = r & 3;
    }
    // consumer permuted lane index (0..31), conflict-free by construction
    const int alane = (lane >> 2) * 4 + ((lane & 3) ^ ((lane >> 2) & 3));

    float acc[4][4][4];
    #pragma unroll
    for (int i = 0; i < 4; i++)
        #pragma unroll
        for (int j = 0; j < 4; j++)
            #pragma unroll
            for (int l = 0; l < 4; l++) acc[i][j][l] = 0.f;

    const int NT = KTOTAL / 16;
    float4 pa[2], pb[2];
    loadA_g<MODE>(pa, c, w_cq, b, m0, ar, ak, 0);
    loadB_g<MODE>(pb, q, Wl, b, n0, ar, ak, 0);

    int p = 0;
    for (int kt = 0; kt < NT; kt++) {
        // commit prefetched tile to smem in fragment-major layout (tf32-rounded)
        #pragma unroll
        for (int h = 0; h < 2; h++) {
            float av[4] = {pa[h].x, pa[h].y, pa[h].z, pa[h].w};
            float bv[4] = {pb[h].x, pb[h].y, pb[h].z, pb[h].w};
            #pragma unroll
            for (int j = 0; j < 4; j++) {
                int cj = j ^ xsel[h];
                As[p][aBase[h] + cj * 4] = f2tf32(av[j]);
                Bs[p][bBase[h] + cj * 2] = f2tf32(bv[j]);
            }
        }
        __syncthreads();

        if (kt + 1 < NT) {
            loadA_g<MODE>(pa, c, w_cq, b, m0, ar, ak, kt + 1);
            loadB_g<MODE>(pb, q, Wl, b, n0, ar, ak, kt + 1);
        }

        // compute on buffer p: 2 k8-blocks, fragments via LDS.128 / LDS.64
        #pragma unroll
        for (int ck = 0; ck < 2; ck++) {
            float4 a4[4];
            float2 b2[4];
            #pragma unroll
            for (int mt = 0; mt < 4; mt++)
                a4[mt] = *(const float4*)&As[p][(((wm * 4 + mt) * 2 + ck) * 32 + alane) * 4];
            #pragma unroll
            for (int nt = 0; nt < 4; nt++)
                b2[nt] = *(const float2*)&Bs[p][(((wn * 4 + nt) * 2 + ck) * 32 + alane) * 2];
            #pragma unroll
            for (int mt = 0; mt < 4; mt++)
                #pragma unroll
                for (int nt = 0; nt < 4; nt++)
                    mma_tf32(acc[mt][nt], (const uint32_t*)&a4[mt], (const uint32_t*)&b2[nt]);
        }
        p ^= 1;
    }

    // ---- epilogue ----
    #pragma unroll
    for (int mt = 0; mt < 4; mt++) {
        int mloc0 = wm * 64 + mt * 16 + (lane >> 2);
        #pragma unroll
        for (int half = 0; half < 2; half++) {
            int mloc = mloc0 + half * 8;
            #pragma unroll
            for (int nt = 0; nt < 4; nt++) {
                float v0 = acc[mt][nt][half * 2 + 0];
                float v1 = acc[mt][nt][half * 2 + 1];
                int col = n0 + wn * 32 + nt * 8 + (lane & 3) * 2;
                if (MODE == 1) {
                    float rb = b_cq[0] + g_rowc[b * CLEN + m0 + mloc];
                    float2 o = make_float2(v0 + rb + g_rowq[b * QLEN + col],
                                           v1 + rb + g_rowq[b * QLEN + col + 1]);
                    *(float2*)(g_S + ((size_t)(b * CLEN + m0 + mloc)) * QLEN + col) = o;
                } else if (MODE == 2) {
                    *(float2*)(g_C2Q + ((size_t)(b * CLEN + m0 + mloc)) * DD + col) =
                        make_float2(v0, v1);
                } else {
                    float2 o = make_float2(v0 + b_l[col], v1 + b_l[col + 1]);
                    *(float2*)(outp + ((size_t)(m0 + mloc)) * DD + col) = o;
                }
            }
        }
    }
}

// ============================ small kernels ============================
__global__ void row_reduce_kernel(const float* __restrict__ c, const float* __restrict__ q,
                                  const float* __restrict__ w_c, const float* __restrict__ b_c,
                                  const float* __restrict__ w_q, const float* __restrict__ b_q) {
    int row = blockIdx.x;
    const float* src; const float* w; const float* bias; float* dst;
    if (row < BB*CLEN) { src = c + (size_t)row*DD; w = w_c; bias = b_c; dst = g_rowc + row; }
    else { int r = row - BB*CLEN; src = q + (size_t)r*DD; w = w_q; bias = b_q; dst = g_rowq + r; }
    float s = 0.f;
    for (int k = threadIdx.x; k < DD; k += 128) s += src[k]*w[k];
    __shared__ float red[128];
    red[threadIdx.x] = s; __syncthreads();
    for (int off = 64; off > 0; off >>= 1) {
        if (threadIdx.x < off) red[threadIdx.x] += red[threadIdx.x+off];
        __syncthreads();
    }
    if (threadIdx.x == 0) dst[0] = red[0] + bias[0];
}

__global__ void transpose_q_kernel(const float* __restrict__ q) {
    __shared__ float t[32][33];
    int b = blockIdx.z;
    int q0 = blockIdx.x * 32, d0 = blockIdx.y * 32;
    for (int i = threadIdx.y; i < 32; i += 8)
        t[i][threadIdx.x] = q[((size_t)b*QLEN + q0 + i)*DD + d0 + threadIdx.x];
    __syncthreads();
    for (int i = threadIdx.y; i < 32; i += 8)
        g_qT[((size_t)b*DD + d0 + i)*QLEN + q0 + threadIdx.x] = t[threadIdx.x][i];
}

__global__ void softmax_q_kernel() {
    int row = blockIdx.x;
    float* s = g_S + (size_t)row*QLEN;
    int t = threadIdx.x;
    float v[4];
    float m = -1e30f;
    #pragma unroll
    for (int i=0;i<4;i++){ v[i] = s[t + i*128]; m = fmaxf(m, v[i]); }
    __shared__ float red[128];
    red[t] = m; __syncthreads();
    for (int off=64; off>0; off>>=1){ if (t<off) red[t]=fmaxf(red[t],red[t+off]); __syncthreads(); }
    float rowmax = red[0];
    __syncthreads();
    float sum = 0.f;
    #pragma unroll
    for (int i=0;i<4;i++){ v[i] = __expf(v[i]-rowmax); sum += v[i]; }
    red[t]=sum; __syncthreads();
    for (int off=64; off>0; off>>=1){ if (t<off) red[t]+=red[t+off]; __syncthreads(); }
    float inv = 1.f/red[0];
    #pragma unroll
    for (int i=0;i<4;i++) s[t+i*128] = v[i]*inv;
    if (t==0) g_M[row]=rowmax;
}

__global__ void batt_kernel() {
    int b = blockIdx.x;
    int t = threadIdx.x;
    float v[8]; float m = -1e30f;
    #pragma unroll
    for (int i=0;i<8;i++){ v[i]=g_M[b*CLEN + t + i*256]; m=fmaxf(m,v[i]); }
    __shared__ float red[256];
    red[t]=m; __syncthreads();
    for (int off=128; off>0; off>>=1){ if (t<off) red[t]=fmaxf(red[t],red[t+off]); __syncthreads(); }
    float mx = red[0];
    __syncthreads();
    float sum = 0.f;
    #pragma unroll
    for (int i=0;i<8;i++){ v[i]=__expf(v[i]-mx); sum+=v[i]; }
    red[t]=sum; __syncthreads();
    for (int off=128; off>0; off>>=1){ if (t<off) red[t]+=red[t+off]; __syncthreads(); }
    float inv = 1.f/red[0];
    #pragma unroll
    for (int i=0;i<8;i++) g_Batt[b*CLEN + t + i*256] = v[i]*inv;
}

__global__ void q2c_part_kernel(const float* __restrict__ c) {
    int j = blockIdx.x;
    int b = blockIdx.y;
    int t = threadIdx.x;
    float acc[4] = {0.f,0.f,0.f,0.f};
    int cbase = j*64;
    const float* cb = c + ((size_t)b*CLEN + cbase)*DD;
    for (int cc=0; cc<64; cc++){
        float w = g_Batt[b*CLEN + cbase + cc];
        const float* row = cb + (size_t)cc*DD;
        #pragma unroll
        for (int i=0;i<4;i++) acc[i] += w * row[t + i*256];
    }
    #pragma unroll
    for (int i=0;i<4;i++) g_Q2Cpart[((size_t)j*BB + b)*DD + t + i*256] = acc[i];
}

__global__ void q2c_reduce_kernel() {
    int idx = blockIdx.x*256 + threadIdx.x;
    int b = idx / DD, d = idx % DD;
    float s = 0.f;
    for (int j=0;j<32;j++) s += g_Q2Cpart[((size_t)j*BB + b)*DD + d];
    g_Q2C[idx] = s;
}

// ============================ launch ============================
extern "C" void kernel_launch(void* const* d_in, const int* in_sizes, int n_in,
                              void* d_out, int out_size) {
    const float* c    = (const float*)d_in[0];
    const float* q    = (const float*)d_in[1];
    const float* w_cq = (const float*)d_in[2];
    const float* b_cq = (const float*)d_in[3];
    const float* w_c  = (const float*)d_in[4];
    const float* b_c  = (const float*)d_in[5];
    const float* w_q  = (const float*)d_in[6];
    const float* b_q  = (const float*)d_in[7];
    const float* W_l  = (const float*)d_in[8];
    const float* b_l  = (const float*)d_in[9];
    float* out = (float*)d_out;

    row_reduce_kernel<<<BB*CLEN + BB*QLEN, 128>>>(c, q, w_c, b_c, w_q, b_q);
    transpose_q_kernel<<<dim3(QLEN/32, DD/32, BB), dim3(32, 8)>>>(q);

    mma_gemm<1, DD><<<dim3(QLEN/128, CLEN/128, BB), 256>>>(
        c, q, W_l, w_cq, b_cq, b_l, out);

    softmax_q_kernel<<<BB*CLEN, 128>>>();
    batt_kernel<<<BB, 256>>>();
    q2c_part_kernel<<<dim3(32, BB), 256>>>(c);
    q2c_reduce_kernel<<<(BB*DD)/256, 256>>>();

    mma_gemm<2, QLEN><<<dim3(DD/128, CLEN/128, BB), 256>>>(
        c, q, W_l, w_cq, b_cq, b_l, out);

    mma_gemm<3, KTOT><<<dim3(DD/128, (BB*CLEN)/128, 1), 256>>>(
        c, q, W_l, w_cq, b_cq, b_l, out);
}